// round 13
// baseline (speedup 1.0000x reference)
#include <cuda_runtime.h>
#include <cuda_fp16.h>
#include <cstdint>

// ---------------------------------------------------------------------------
// NetVLAD GB300 round 12: s-tile 96 (288 blocks = single wave @2 CTA/SM),
// register-resident norm epilogue, fully-HMMA logits+vlad.
// N=32, C=1024, D=128, K=64, S=784 (9 tiles of 96), OUT=1024
// ---------------------------------------------------------------------------

__device__ __align__(16) unsigned char g_wpk[589824];  // 16 chunks x 36864B W image
__device__ __align__(16) unsigned char g_wcpk[17408];  // Wconv fp16 [64 k][272B]
__device__ float g_vladraw[32 * 8192];
__device__ float g_vlad  [32 * 8192];
__device__ float g_sasum [32 * 64];
__device__ float g_proj  [32 * 1024];

#define FMA2(acc, a, b) \
    asm("fma.rn.f32x2 %0, %1, %2, %0;" : "+l"(acc) : "l"(a), "l"(b))
#define DUP2(d, s) \
    asm("mov.b64 %0, {%1, %1};" : "=l"(d) : "f"(s))
#define UNPK(lo, hi, s) \
    asm("mov.b64 {%0, %1}, %2;" : "=f"(lo), "=f"(hi) : "l"(s))

__device__ __forceinline__ uint32_t smem_u32(const void* p) {
    uint32_t a;
    asm("{ .reg .u64 t; cvta.to.shared.u64 t, %1; cvt.u32.u64 %0, t; }"
        : "=r"(a) : "l"(p));
    return a;
}
__device__ __forceinline__ void cpasync16(uint32_t smem, const void* gmem) {
    asm volatile("cp.async.cg.shared.global [%0], [%1], 16;"
        :: "r"(smem), "l"(gmem) : "memory");
}
#define CP_COMMIT() asm volatile("cp.async.commit_group;" ::: "memory")
#define CP_WAIT1()  asm volatile("cp.async.wait_group 1;" ::: "memory")

__device__ __forceinline__ void ldsm(unsigned* r, uint32_t a) {
    asm volatile("ldmatrix.sync.aligned.m8n8.x4.shared.b16 {%0,%1,%2,%3}, [%4];"
        : "=r"(r[0]), "=r"(r[1]), "=r"(r[2]), "=r"(r[3]) : "r"(a));
}
__device__ __forceinline__ void ldsmt(unsigned* r, uint32_t a) {
    asm volatile("ldmatrix.sync.aligned.m8n8.x4.trans.shared.b16 {%0,%1,%2,%3}, [%4];"
        : "=r"(r[0]), "=r"(r[1]), "=r"(r[2]), "=r"(r[3]) : "r"(a));
}
__device__ __forceinline__ void mma_f16(float* c, const unsigned* a, const unsigned* b) {
    asm volatile(
        "mma.sync.aligned.m16n8k16.row.col.f32.f16.f16.f32 "
        "{%0,%1,%2,%3}, {%4,%5,%6,%7}, {%8,%9}, {%0,%1,%2,%3};"
        : "+f"(c[0]), "+f"(c[1]), "+f"(c[2]), "+f"(c[3])
        : "r"(a[0]), "r"(a[1]), "r"(a[2]), "r"(a[3]), "r"(b[0]), "r"(b[1]));
}

// ---------------------------------------------------------------------------
// kInit: zero accumulators + pack Wpool fp16 hi/lo image + Wconv fp16 image
// ---------------------------------------------------------------------------
__global__ void kInit(const float* __restrict__ Wpool,
                      const float* __restrict__ Wconv) {
    int idx = blockIdx.x * 256 + threadIdx.x;
    if (idx < 262144) g_vladraw[idx] = 0.f;
    if (idx < 2048)   g_sasum[idx] = 0.f;
    if (idx < 32768)  g_proj[idx] = 0.f;
    if (idx < 131072) {
        int d = idx >> 10, c = idx & 1023;
        float w = Wpool[idx];
        __half h = __float2half_rn(w);
        __half l = __float2half_rn(w - __half2float(h));
        int q = c >> 6, cl = c & 63;
        *(__half*)(g_wpk + q * 36864 + d * 144 + cl * 2) = h;
        *(__half*)(g_wpk + q * 36864 + 18432 + d * 144 + cl * 2) = l;
    }
    if (idx < 8192) {
        int k = idx >> 7, d = idx & 127;
        *(__half*)(g_wcpk + k * 272 + d * 2) = __float2half_rn(Wconv[idx]);
    }
}

// ---------------------------------------------------------------------------
// kA: fp16 2-term mma pool GEMM (128d x 96s) + register-norm + HMMA epilogue
// grid (9, 32), 256 thr, dyn smem 110976 B
// phase1: BUF(b) @ 1024 + b*50176: WH 18432 | WL 18432 | X 13312 (64c x 208B)
// phase2 (bytes):
//   XF16_ds @1024  [128 d][208B]  (logits B)
//   XF16_sd @27648 [96 s][272B]   (vlad B)
//   saA     @53760 [64 k][208B]
//   part/inv then EP_log @67072   (part [96][4]f, inv [96]f; EP_log [96][69]f)
//   WcA     @93568 [64 k][272B]
// ---------------------------------------------------------------------------
__global__ void __launch_bounds__(256, 2) kA(const float* __restrict__ x,
                                             const float* __restrict__ bpool,
                                             const float* __restrict__ bconv) {
    extern __shared__ char smc[];
    float* smf = (float*)smc;
    const uint32_t sb = smem_u32(smc);

    const int tid = threadIdx.x, lane = tid & 31, wid = tid >> 5;
    const int n = blockIdx.y;
    const int s0 = blockIdx.x * 96;
    const bool fullv = (blockIdx.x < 8);

    const float* xn = x + (size_t)n * 1024 * 784;
    const int xc = tid >> 2, xs = (tid & 3) * 24;

    const int wd = wid & 3, ws = wid >> 2;
    const int md0 = wd * 32, ns0 = ws * 48;
    const int mat = lane >> 3, rr = lane & 7;
    const int r0w = lane >> 2, cq = lane & 3;
    const uint32_t aH0 = sb + 1024 + (uint32_t)(md0 + ((mat & 1) << 3) + rr) * 144
                         + ((uint32_t)(mat >> 1) << 4);
    const uint32_t bH0 = sb + 1024 + 36864 + (uint32_t)(((mat & 1) << 3) + rr) * 208
                         + (uint32_t)(ns0 + ((mat >> 1) << 3)) * 2;

    float acc[2][6][4];
#pragma unroll
    for (int mt = 0; mt < 2; mt++)
#pragma unroll
        for (int nf = 0; nf < 6; nf++)
#pragma unroll
            for (int u = 0; u < 4; u++) acc[mt][nf][u] = 0.f;

    uint32_t xh2[12];

#define LOADX(q) do { \
    const float* p0 = xn + (size_t)((q) * 64 + xc) * 784 + s0 + xs; \
    if (fullv) { \
        _Pragma("unroll") \
        for (int u = 0; u < 6; u++) { \
            float4 a4 = ((const float4*)p0)[u]; \
            __half2 h0 = __floats2half2_rn(a4.x, a4.y); \
            __half2 h1 = __floats2half2_rn(a4.z, a4.w); \
            xh2[u * 2]     = *(uint32_t*)&h0; \
            xh2[u * 2 + 1] = *(uint32_t*)&h1; \
        } \
    } else { \
        _Pragma("unroll") \
        for (int i = 0; i < 12; i++) { \
            float v0 = ((s0 + xs + 2 * i)     < 784) ? p0[2 * i]     : 0.f; \
            float v1 = ((s0 + xs + 2 * i + 1) < 784) ? p0[2 * i + 1] : 0.f; \
            __half2 hp = __floats2half2_rn(v0, v1); \
            xh2[i] = *(uint32_t*)&hp; \
        } \
    } } while (0)

#define STOREX(b) do { \
    char* xd = smc + 1024 + (b) * 50176 + 36864 + xc * 208 + xs * 2; \
    _Pragma("unroll") \
    for (int i = 0; i < 12; i++) *(uint32_t*)(xd + i * 4) = xh2[i]; \
    } while (0)

#define COPYW(q, b) do { \
    const unsigned char* src = g_wpk + (q) * 36864; \
    uint32_t dst = sb + 1024 + (b) * 50176; \
    _Pragma("unroll") \
    for (int i = 0; i < 9; i++) { \
        int seg = tid + i * 256; \
        cpasync16(dst + seg * 16, src + seg * 16); \
    } } while (0)

    LOADX(0);
    COPYW(0, 0); CP_COMMIT();
    COPYW(1, 1); CP_COMMIT();

    for (int q = 0; q < 16; q++) {
        const int b = q & 1;
        STOREX(b);
        if (q + 1 < 16) LOADX(q + 1);
        CP_WAIT1();
        __syncthreads();

        const uint32_t aH = aH0 + b * 50176;
        const uint32_t aL = aH + 18432;
        const uint32_t bH = bH0 + b * 50176;
#pragma unroll
        for (int ks = 0; ks < 4; ks++) {
            unsigned ah[2][4], al[2][4];
            ldsm(ah[0], aH + ks * 32);
            ldsm(ah[1], aH + ks * 32 + 2304);
            ldsm(al[0], aL + ks * 32);
            ldsm(al[1], aL + ks * 32 + 2304);
            unsigned bh[3][4];
#pragma unroll
            for (int nt = 0; nt < 3; nt++)
                ldsmt(bh[nt], bH + ks * 3328 + nt * 32);
#pragma unroll
            for (int mt = 0; mt < 2; mt++)
#pragma unroll
                for (int nf = 0; nf < 6; nf++) {
                    const unsigned* bhf = &bh[nf >> 1][(nf & 1) * 2];
                    mma_f16(acc[mt][nf], ah[mt], bhf);
                    mma_f16(acc[mt][nf], al[mt], bhf);
                }
        }
        __syncthreads();
        if (q + 2 < 16) COPYW(q + 2, b);
        CP_COMMIT();
    }
#undef LOADX
#undef STOREX
#undef COPYW

    // ---- bias add (in registers) ----
    {
        float b00 = __ldg(&bpool[md0 + r0w]);
        float b01 = __ldg(&bpool[md0 + r0w + 8]);
        float b10 = __ldg(&bpool[md0 + 16 + r0w]);
        float b11 = __ldg(&bpool[md0 + 24 + r0w]);
#pragma unroll
        for (int nf = 0; nf < 6; nf++) {
            acc[0][nf][0] += b00; acc[0][nf][1] += b00;
            acc[0][nf][2] += b01; acc[0][nf][3] += b01;
            acc[1][nf][0] += b10; acc[1][nf][1] += b10;
            acc[1][nf][2] += b11; acc[1][nf][3] += b11;
        }
    }

    // ---- stage WcA (Wconv fp16 image) into dead buffer-1 region ----
    {
        const uint4* src = (const uint4*)g_wcpk;
        uint4* dst = (uint4*)(smc + 93568);
#pragma unroll
        for (int i = 0; i < 5; i++) {
            int seg = tid + i * 256;
            if (seg < 1088) dst[seg] = src[seg];
        }
    }

    // ---- column sumsq: shuffle-reduce over r0w, store part[s][wd] ----
    {
        float psq[12];
#pragma unroll
        for (int nf = 0; nf < 6; nf++)
#pragma unroll
            for (int j = 0; j < 2; j++) {
                float p = acc[0][nf][j] * acc[0][nf][j]
                        + acc[0][nf][j + 2] * acc[0][nf][j + 2]
                        + acc[1][nf][j] * acc[1][nf][j]
                        + acc[1][nf][j + 2] * acc[1][nf][j + 2];
#pragma unroll
                for (int off = 4; off <= 16; off <<= 1)
                    p += __shfl_xor_sync(0xffffffffu, p, off);
                psq[nf * 2 + j] = p;
            }
        if (r0w == 0) {
#pragma unroll
            for (int nf = 0; nf < 6; nf++)
#pragma unroll
                for (int j = 0; j < 2; j++) {
                    int s = ns0 + nf * 8 + cq * 2 + j;
                    smf[16768 + s * 4 + wd] = psq[nf * 2 + j];
                }
        }
    }
    __syncthreads();
    if (tid < 96) {
        float t = smf[16768 + tid * 4] + smf[16768 + tid * 4 + 1]
                + smf[16768 + tid * 4 + 2] + smf[16768 + tid * 4 + 3];
        smf[17152 + tid] = ((s0 + tid) < 784) ? 1.f / fmaxf(sqrtf(t), 1e-12f) : 0.f;
    }
    __syncthreads();

    // ---- normalize + write fp16 tiles (XF16_ds and XF16_sd) directly ----
#pragma unroll
    for (int nf = 0; nf < 6; nf++) {
        int sA = ns0 + nf * 8 + cq * 2;
        float i0 = smf[17152 + sA], i1 = smf[17152 + sA + 1];
#pragma unroll
        for (int mt = 0; mt < 2; mt++) {
            int d0 = md0 + mt * 16 + r0w, d1 = d0 + 8;
            __half2 hA = __floats2half2_rn(acc[mt][nf][0] * i0, acc[mt][nf][1] * i1);
            __half2 hB = __floats2half2_rn(acc[mt][nf][2] * i0, acc[mt][nf][3] * i1);
            *(uint32_t*)(smc + 1024 + d0 * 208 + sA * 2) = *(uint32_t*)&hA;
            *(uint32_t*)(smc + 1024 + d1 * 208 + sA * 2) = *(uint32_t*)&hB;
            *(__half*)(smc + 27648 + sA * 272 + d0 * 2)       = __low2half(hA);
            *(__half*)(smc + 27648 + (sA + 1) * 272 + d0 * 2) = __high2half(hA);
            *(__half*)(smc + 27648 + sA * 272 + d1 * 2)       = __low2half(hB);
            *(__half*)(smc + 27648 + (sA + 1) * 272 + d1 * 2) = __high2half(hB);
        }
    }
    __syncthreads();

    // ---- logits mma: M=64(k) N=96(s) K=128(d) ----
    {
        const uint32_t aW = sb + 93568 + (uint32_t)(16 * wd + ((mat & 1) << 3) + rr) * 272
                            + ((uint32_t)(mat >> 1) << 4);
        const uint32_t bL = sb + 1024 + (uint32_t)(((mat & 1) << 3) + rr) * 208
                            + (uint32_t)(ns0 + ((mat >> 1) << 3)) * 2;
        float accl[6][4];
#pragma unroll
        for (int nf = 0; nf < 6; nf++)
#pragma unroll
            for (int u = 0; u < 4; u++) accl[nf][u] = 0.f;
#pragma unroll
        for (int ks = 0; ks < 8; ks++) {
            unsigned a[4];
            ldsm(a, aW + ks * 32);
            unsigned bb[3][4];
#pragma unroll
            for (int nt = 0; nt < 3; nt++)
                ldsmt(bb[nt], bL + ks * 3328 + nt * 32);
#pragma unroll
            for (int nf = 0; nf < 6; nf++)
                mma_f16(accl[nf], a, &bb[nf >> 1][(nf & 1) * 2]);
        }
        float bc0 = __ldg(&bconv[16 * wd + r0w]);
        float bc1 = __ldg(&bconv[16 * wd + r0w + 8]);
#pragma unroll
        for (int nf = 0; nf < 6; nf++) {
            int s = ns0 + nf * 8 + cq * 2;
            int k = 16 * wd + r0w;
            smf[16768 + s * 69 + k]           = accl[nf][0] + bc0;
            smf[16768 + (s + 1) * 69 + k]     = accl[nf][1] + bc0;
            smf[16768 + s * 69 + k + 8]       = accl[nf][2] + bc1;
            smf[16768 + (s + 1) * 69 + k + 8] = accl[nf][3] + bc1;
        }
    }
    __syncthreads();

    // ---- softmax over K=64 per s-column (tid<96 owns one column) ----
    if (tid < 96) {
        float* row = &smf[16768 + tid * 69];
        float mx = -1e30f;
#pragma unroll 8
        for (int k = 0; k < 64; k++) mx = fmaxf(mx, row[k]);
        float ssum = 0.f;
#pragma unroll 8
        for (int k = 0; k < 64; k++) {
            float e = __expf(row[k] - mx);
            row[k] = e;
            ssum += e;
        }
        float r = ((s0 + tid) < 784) ? 1.f / ssum : 0.f;
#pragma unroll 8
        for (int k = 0; k < 64; k++)
            *(__half*)(smc + 53760 + k * 208 + tid * 2) = __float2half_rn(row[k] * r);
    }
    __syncthreads();

    // ---- sasum from rounded sa ----
    if (tid < 64) {
        const __half2* rp = (const __half2*)(smc + 53760 + tid * 208);
        float s = 0.f;
#pragma unroll
        for (int i = 0; i < 48; i++) {
            float2 f = __half22float2(rp[i]);
            s += f.x + f.y;
        }
        atomicAdd(&g_sasum[n * 64 + tid], s);
    }

    // ---- vlad mma: M=64(k) N=128(d) K=96(s) -> atomicAdd g_vladraw ----
    {
        const uint32_t aV = sb + 53760 + (uint32_t)(16 * wd + ((mat & 1) << 3) + rr) * 208
                            + ((uint32_t)(mat >> 1) << 4);
        const uint32_t bV = sb + 27648 + (uint32_t)(((mat & 1) << 3) + rr) * 272
                            + (uint32_t)(64 * ws + ((mat >> 1) << 3)) * 2;
        float accv[8][4];
#pragma unroll
        for (int nf = 0; nf < 8; nf++)
#pragma unroll
            for (int u = 0; u < 4; u++) accv[nf][u] = 0.f;
#pragma unroll
        for (int ks = 0; ks < 6; ks++) {
            unsigned a[4];
            ldsm(a, aV + ks * 32);
            unsigned bb[4][4];
#pragma unroll
            for (int nt = 0; nt < 4; nt++)
                ldsmt(bb[nt], bV + ks * 4352 + nt * 32);
#pragma unroll
            for (int nf = 0; nf < 8; nf++)
                mma_f16(accv[nf], a, &bb[nf >> 1][(nf & 1) * 2]);
        }
        float* vr = g_vladraw + (size_t)n * 8192;
        const int k0 = 16 * wd + r0w, k1 = k0 + 8;
#pragma unroll
        for (int nf = 0; nf < 8; nf++) {
            int d = 64 * ws + nf * 8 + cq * 2;
            atomicAdd(&vr[k0 * 128 + d],     accv[nf][0]);
            atomicAdd(&vr[k0 * 128 + d + 1], accv[nf][1]);
            atomicAdd(&vr[k1 * 128 + d],     accv[nf][2]);
            atomicAdd(&vr[k1 * 128 + d + 1], accv[nf][3]);
        }
    }
}

// ---------------------------------------------------------------------------
// kBfin: vlad = vladraw - centroids*sasum, intra-norm over K
// ---------------------------------------------------------------------------
__global__ void __launch_bounds__(256) kBfin(const float* __restrict__ centroids) {
    __shared__ float ssm[64];
    __shared__ float red[8][33];
    const int dt = blockIdx.x, n = blockIdx.y, tid = threadIdx.x;
    const int dl = tid & 31, kg = tid >> 5;
    const int d = dt * 32 + dl;
    if (tid < 64) ssm[tid] = g_sasum[n * 64 + tid];
    __syncthreads();
    const float* vr = g_vladraw + (size_t)n * 8192;
    float v[8], sq = 0.f;
#pragma unroll
    for (int j = 0; j < 8; j++) {
        int k = kg * 8 + j;
        float val = vr[k * 128 + d] - centroids[k * 128 + d] * ssm[k];
        v[j] = val;
        sq += val * val;
    }
    red[kg][dl] = sq;
    __syncthreads();
    float tot = 0.f;
#pragma unroll
    for (int t = 0; t < 8; t++) tot += red[t][dl];
    float inv = 1.f / fmaxf(sqrtf(tot), 1e-12f);
    float* vo = g_vlad + (size_t)n * 8192;
#pragma unroll
    for (int j = 0; j < 8; j++)
        vo[(kg * 8 + j) * 128 + d] = v[j] * inv;
}

// ---------------------------------------------------------------------------
// kC: proj += vlad @ Wproj^T.  grid (8 o-tiles of 128, 16 j-splits of 512)
// ---------------------------------------------------------------------------
__global__ void __launch_bounds__(256) kC(const float* __restrict__ Wproj) {
    __shared__ float wT[32 * 132];
    __shared__ float vT[32 * 36];
    const int tid = threadIdx.x;
    const int ob = blockIdx.x * 128;
    const int jb = blockIdx.y * 512;
    const int og = tid >> 4;
    const int ng = tid & 15;

    unsigned long long acc[8];
#pragma unroll
    for (int i = 0; i < 8; i++) acc[i] = 0ull;

    const int wo = tid >> 1, wj = (tid & 1) * 16;
    const int vn = tid >> 3, vj = (tid & 7) * 4;

    for (int jt = 0; jt < 512; jt += 32) {
        __syncthreads();
        {
            const float* wr = &Wproj[(size_t)(ob + wo) * 8192 + jb + jt + wj];
#pragma unroll
            for (int u = 0; u < 4; u++) {
                float4 w = *(const float4*)&wr[u * 4];
                wT[(wj + u * 4 + 0) * 132 + wo] = w.x;
                wT[(wj + u * 4 + 1) * 132 + wo] = w.y;
                wT[(wj + u * 4 + 2) * 132 + wo] = w.z;
                wT[(wj + u * 4 + 3) * 132 + wo] = w.w;
            }
            float4 v = *(const float4*)&g_vlad[(size_t)vn * 8192 + jb + jt + vj];
            vT[(vj + 0) * 36 + vn] = v.x;
            vT[(vj + 1) * 36 + vn] = v.y;
            vT[(vj + 2) * 36 + vn] = v.z;
            vT[(vj + 3) * 36 + vn] = v.w;
        }
        __syncthreads();
#pragma unroll
        for (int j = 0; j < 32; j++) {
            float4 w0 = *(const float4*)&wT[j * 132 + og * 8];
            float4 w1 = *(const float4*)&wT[j * 132 + og * 8 + 4];
            unsigned long long vp = *(const unsigned long long*)&vT[j * 36 + ng * 2];
            unsigned long long wdr[8];
            DUP2(wdr[0], w0.x); DUP2(wdr[1], w0.y); DUP2(wdr[2], w0.z); DUP2(wdr[3], w0.w);
            DUP2(wdr[4], w1.x); DUP2(wdr[5], w1.y); DUP2(wdr[6], w1.z); DUP2(wdr[7], w1.w);
#pragma unroll
            for (int i = 0; i < 8; i++) FMA2(acc[i], wdr[i], vp);
        }
    }
#pragma unroll
    for (int i = 0; i < 8; i++) {
        float lo, hi;
        UNPK(lo, hi, acc[i]);
        int o = ob + og * 8 + i;
        atomicAdd(&g_proj[(ng * 2 + 0) * 1024 + o], lo);
        atomicAdd(&g_proj[(ng * 2 + 1) * 1024 + o], hi);
    }
}

// ---------------------------------------------------------------------------
__global__ void __launch_bounds__(256) kD(const float* __restrict__ bproj,
                                          float* __restrict__ out) {
    __shared__ float wr[8];
    __shared__ float inv_s;
    const int n = blockIdx.x, tid = threadIdx.x;
    float v[4]; float ps = 0.f;
#pragma unroll
    for (int r = 0; r < 4; r++) {
        int o = r * 256 + tid;
        v[r] = g_proj[n * 1024 + o] + bproj[o];
        ps += v[r] * v[r];
    }
#pragma unroll
    for (int off = 16; off; off >>= 1)
        ps += __shfl_xor_sync(0xffffffffu, ps, off);
    if ((tid & 31) == 0) wr[tid >> 5] = ps;
    __syncthreads();
    if (tid == 0) {
        float s = 0.f;
#pragma unroll
        for (int t = 0; t < 8; t++) s += wr[t];
        inv_s = 1.f / fmaxf(sqrtf(s), 1e-12f);
    }
    __syncthreads();
#pragma unroll
    for (int r = 0; r < 4; r++)
        out[n * 1024 + r * 256 + tid] = v[r] * inv_s;
}

// ---------------------------------------------------------------------------
extern "C" void kernel_launch(void* const* d_in, const int* in_sizes, int n_in,
                              void* d_out, int out_size) {
    const float* x         = (const float*)d_in[0];
    const float* Wpool     = (const float*)d_in[1];
    const float* bpool     = (const float*)d_in[2];
    const float* Wconv     = (const float*)d_in[3];
    const float* bconv     = (const float*)d_in[4];
    const float* centroids = (const float*)d_in[5];
    const float* Wproj     = (const float*)d_in[6];
    const float* bproj     = (const float*)d_in[7];
    float* out = (float*)d_out;

    cudaFuncSetAttribute(kA, cudaFuncAttributeMaxDynamicSharedMemorySize, 110976);

    kInit<<<1024, 256>>>(Wpool, Wconv);
    dim3 gA(9, 32);
    kA<<<gA, 256, 110976>>>(x, bpool, bconv);
    dim3 gB(4, 32);
    kBfin<<<gB, 256>>>(centroids);
    dim3 gC(8, 16);
    kC<<<gC, 256>>>(Wproj);
    kD<<<32, 256>>>(bproj, out);
}

// round 14
// speedup vs baseline: 1.2472x; 1.2472x over previous
#include <cuda_runtime.h>
#include <cuda_fp16.h>
#include <cstdint>

// ---------------------------------------------------------------------------
// NetVLAD GB300 round 13: R11 kA (s=64) + HMMA kC
// N=32, C=1024, D=128, K=64, S=784 (13 tiles of 64), OUT=1024
// ---------------------------------------------------------------------------

__device__ __align__(16) unsigned char g_wpk[589824];  // 16 chunks x 36864B W image
__device__ __align__(16) unsigned char g_wcpk[17408];  // Wconv fp16 [64 k][272B]
__device__ float g_vladraw[32 * 8192];
__device__ float g_vlad  [32 * 8192];
__device__ float g_sasum [32 * 64];
__device__ float g_proj  [32 * 1024];

__device__ __forceinline__ uint32_t smem_u32(const void* p) {
    uint32_t a;
    asm("{ .reg .u64 t; cvta.to.shared.u64 t, %1; cvt.u32.u64 %0, t; }"
        : "=r"(a) : "l"(p));
    return a;
}
__device__ __forceinline__ void cpasync16(uint32_t smem, const void* gmem) {
    asm volatile("cp.async.cg.shared.global [%0], [%1], 16;"
        :: "r"(smem), "l"(gmem) : "memory");
}
#define CP_COMMIT() asm volatile("cp.async.commit_group;" ::: "memory")
#define CP_WAIT1()  asm volatile("cp.async.wait_group 1;" ::: "memory")

__device__ __forceinline__ void ldsm(unsigned* r, uint32_t a) {
    asm volatile("ldmatrix.sync.aligned.m8n8.x4.shared.b16 {%0,%1,%2,%3}, [%4];"
        : "=r"(r[0]), "=r"(r[1]), "=r"(r[2]), "=r"(r[3]) : "r"(a));
}
__device__ __forceinline__ void ldsmt(unsigned* r, uint32_t a) {
    asm volatile("ldmatrix.sync.aligned.m8n8.x4.trans.shared.b16 {%0,%1,%2,%3}, [%4];"
        : "=r"(r[0]), "=r"(r[1]), "=r"(r[2]), "=r"(r[3]) : "r"(a));
}
__device__ __forceinline__ void mma_f16(float* c, const unsigned* a, const unsigned* b) {
    asm volatile(
        "mma.sync.aligned.m16n8k16.row.col.f32.f16.f16.f32 "
        "{%0,%1,%2,%3}, {%4,%5,%6,%7}, {%8,%9}, {%0,%1,%2,%3};"
        : "+f"(c[0]), "+f"(c[1]), "+f"(c[2]), "+f"(c[3])
        : "r"(a[0]), "r"(a[1]), "r"(a[2]), "r"(a[3]), "r"(b[0]), "r"(b[1]));
}

// ---------------------------------------------------------------------------
__global__ void kW(const float* __restrict__ Wpool) {
    int idx = blockIdx.x * 256 + threadIdx.x;
    if (idx >= 131072) return;
    int d = idx >> 10, c = idx & 1023;
    float w = Wpool[idx];
    __half h = __float2half_rn(w);
    __half l = __float2half_rn(w - __half2float(h));
    int q = c >> 6, cl = c & 63;
    *(__half*)(g_wpk + q * 36864 + d * 144 + cl * 2) = h;
    *(__half*)(g_wpk + q * 36864 + 18432 + d * 144 + cl * 2) = l;
}

__global__ void kZ(const float* __restrict__ Wconv) {
    int idx = blockIdx.x * 256 + threadIdx.x;
    if (idx < 262144) g_vladraw[idx] = 0.f;
    if (idx < 2048)   g_sasum[idx] = 0.f;
    if (idx < 32768)  g_proj[idx] = 0.f;
    if (idx < 8192) {
        int k = idx >> 7, d = idx & 127;
        *(__half*)(g_wcpk + k * 272 + d * 2) = __float2half_rn(Wconv[idx]);
    }
}

// ---------------------------------------------------------------------------
// kA: fp16 2-term mma pool GEMM (128d x 64s) + fully-HMMA epilogue
// grid (13, 32), 256 thr, dyn smem 93184 B  (R11 version, verbatim)
// ---------------------------------------------------------------------------
__global__ void __launch_bounds__(256, 2) kA(const float* __restrict__ x,
                                             const float* __restrict__ bpool,
                                             const float* __restrict__ bconv) {
    extern __shared__ char smc[];
    float* smf = (float*)smc;
    const uint32_t sb = smem_u32(smc);

    const int tid = threadIdx.x, lane = tid & 31, wid = tid >> 5;
    const int n = blockIdx.y;
    const int s0 = blockIdx.x * 64;
    const bool fullv = (blockIdx.x < 12);

    const float* xn = x + (size_t)n * 1024 * 784;
    const int xc = tid >> 2, xs = (tid & 3) * 16;

    const int wd = wid & 3, ws = wid >> 2;
    const int md0 = wd * 32, ns0 = ws * 32;
    const int mat = lane >> 3, rr = lane & 7;
    const uint32_t aH0 = sb + 1024 + (uint32_t)(md0 + ((mat & 1) << 3) + rr) * 144
                         + ((uint32_t)(mat >> 1) << 4);
    const uint32_t bH0 = sb + 1024 + 36864 + (uint32_t)(((mat & 1) << 3) + rr) * 144
                         + (uint32_t)(ns0 + ((mat >> 1) << 3)) * 2;

    float acc[2][4][4];
#pragma unroll
    for (int mt = 0; mt < 2; mt++)
#pragma unroll
        for (int nf = 0; nf < 4; nf++)
#pragma unroll
            for (int u = 0; u < 4; u++) acc[mt][nf][u] = 0.f;

    float xr[16];

#define LOADX(q) do { \
    const float* p0 = xn + (size_t)((q) * 64 + xc) * 784 + s0 + xs; \
    if (fullv) { \
        _Pragma("unroll") \
        for (int u = 0; u < 4; u++) { \
            float4 a4 = ((const float4*)p0)[u]; \
            xr[u * 4] = a4.x; xr[u * 4 + 1] = a4.y; \
            xr[u * 4 + 2] = a4.z; xr[u * 4 + 3] = a4.w; \
        } \
    } else { \
        _Pragma("unroll") \
        for (int i = 0; i < 16; i++) \
            xr[i] = ((s0 + xs + i) < 784) ? p0[i] : 0.f; \
    } } while (0)

#define STOREX(b) do { \
    char* xh = smc + 1024 + (b) * 46080 + 36864 + xc * 144 + xs * 2; \
    _Pragma("unroll") \
    for (int i = 0; i < 8; i++) { \
        __half2 hp = __floats2half2_rn(xr[2 * i], xr[2 * i + 1]); \
        *(uint32_t*)(xh + i * 4) = *(uint32_t*)&hp; \
    } } while (0)

#define COPYW(q, b) do { \
    const unsigned char* src = g_wpk + (q) * 36864; \
    uint32_t dst = sb + 1024 + (b) * 46080; \
    _Pragma("unroll") \
    for (int i = 0; i < 9; i++) { \
        int seg = tid + i * 256; \
        cpasync16(dst + seg * 16, src + seg * 16); \
    } } while (0)

    LOADX(0);
    COPYW(0, 0); CP_COMMIT();
    COPYW(1, 1); CP_COMMIT();

    for (int q = 0; q < 16; q++) {
        const int b = q & 1;
        STOREX(b);
        if (q + 1 < 16) LOADX(q + 1);
        CP_WAIT1();
        __syncthreads();

        const uint32_t aH = aH0 + b * 46080;
        const uint32_t aL = aH + 18432;
        const uint32_t bH = bH0 + b * 46080;
#pragma unroll
        for (int ks = 0; ks < 4; ks++) {
            unsigned ah[2][4], al[2][4];
            ldsm(ah[0], aH + ks * 32);
            ldsm(ah[1], aH + ks * 32 + 2304);
            ldsm(al[0], aL + ks * 32);
            ldsm(al[1], aL + ks * 32 + 2304);
            unsigned bh[2][4];
#pragma unroll
            for (int nt = 0; nt < 2; nt++)
                ldsmt(bh[nt], bH + ks * 2304 + nt * 32);
#pragma unroll
            for (int mt = 0; mt < 2; mt++)
#pragma unroll
                for (int nf = 0; nf < 4; nf++) {
                    const unsigned* bhf = &bh[nf >> 1][(nf & 1) * 2];
                    mma_f16(acc[mt][nf], ah[mt], bhf);
                    mma_f16(acc[mt][nf], al[mt], bhf);
                }
        }
        __syncthreads();
        if (q + 2 < 16) COPYW(q + 2, b);
        CP_COMMIT();
    }
#undef LOADX
#undef STOREX
#undef COPYW

    const int r0w = lane >> 2, cq = lane & 3;

    // ---- acc -> XF_A[d][68 s] fp32 (+bias) ----
    {
#pragma unroll
        for (int mt = 0; mt < 2; mt++) {
            int d = md0 + mt * 16 + r0w;
            float b0 = __ldg(&bpool[d]);
            float b8 = __ldg(&bpool[d + 8]);
#pragma unroll
            for (int nf = 0; nf < 4; nf++) {
                int s = ns0 + nf * 8 + cq * 2;
                smf[256 + d * 68 + s]           = acc[mt][nf][0] + b0;
                smf[256 + d * 68 + s + 1]       = acc[mt][nf][1] + b0;
                smf[256 + (d + 8) * 68 + s]     = acc[mt][nf][2] + b8;
                smf[256 + (d + 8) * 68 + s + 1] = acc[mt][nf][3] + b8;
            }
        }
    }
    __syncthreads();

    // ---- column L2 norm over d ----
    if (tid < 64) {
        float s = 0.f;
#pragma unroll 8
        for (int d = 0; d < 128; d++) {
            float v = smf[256 + d * 68 + tid];
            s += v * v;
        }
        smf[17920 + tid] = ((s0 + tid) < 784) ? 1.f / fmaxf(sqrtf(s), 1e-12f) : 0.f;
    }
    __syncthreads();

    // ---- build fp16 xf tiles: XF16_ds [d][144B] and XF16_sd [s][272B] ----
    {
        const int row = tid & 127, hs = tid >> 7;
#pragma unroll
        for (int g = 0; g < 8; g++) {
            int s4 = hs * 32 + g * 4;
            float4 v = *(const float4*)&smf[256 + row * 68 + s4];
            float4 m = *(const float4*)&smf[17920 + s4];
            v.x *= m.x; v.y *= m.y; v.z *= m.z; v.w *= m.w;
            __half2 h01 = __floats2half2_rn(v.x, v.y);
            __half2 h23 = __floats2half2_rn(v.z, v.w);
            *(uint32_t*)(smc + 35840 + row * 144 + s4 * 2)     = *(uint32_t*)&h01;
            *(uint32_t*)(smc + 35840 + row * 144 + s4 * 2 + 4) = *(uint32_t*)&h23;
            *(__half*)(smc + 54272 + (s4 + 0) * 272 + row * 2) = __low2half(h01);
            *(__half*)(smc + 54272 + (s4 + 1) * 272 + row * 2) = __high2half(h01);
            *(__half*)(smc + 54272 + (s4 + 2) * 272 + row * 2) = __low2half(h23);
            *(__half*)(smc + 54272 + (s4 + 3) * 272 + row * 2) = __high2half(h23);
        }
    }
    __syncthreads();

    // ---- copy Wconv fp16 image into regionA ----
    {
        const uint4* src = (const uint4*)g_wcpk;
        uint4* dst = (uint4*)(smc + 1024);
#pragma unroll
        for (int i = 0; i < 5; i++) {
            int seg = tid + i * 256;
            if (seg < 1088) dst[seg] = src[seg];
        }
    }
    __syncthreads();

    // ---- logits mma: M=64(k) N=64(s) K=128(d) ----
    float accl[4][4];
#pragma unroll
    for (int nf = 0; nf < 4; nf++)
#pragma unroll
        for (int u = 0; u < 4; u++) accl[nf][u] = 0.f;
    {
        const uint32_t aW = sb + 1024 + (uint32_t)(16 * wd + ((mat & 1) << 3) + rr) * 272
                            + ((uint32_t)(mat >> 1) << 4);
        const uint32_t bL = sb + 35840 + (uint32_t)(((mat & 1) << 3) + rr) * 144
                            + (uint32_t)(32 * ws + ((mat >> 1) << 3)) * 2;
#pragma unroll
        for (int ks = 0; ks < 8; ks++) {
            unsigned a[4];
            ldsm(a, aW + ks * 32);
            unsigned bb[2][4];
            ldsmt(bb[0], bL + ks * 2304);
            ldsmt(bb[1], bL + ks * 2304 + 32);
#pragma unroll
            for (int nf = 0; nf < 4; nf++)
                mma_f16(accl[nf], a, &bb[nf >> 1][(nf & 1) * 2]);
        }
    }
    __syncthreads();

    // ---- bias + store logits -> EP_log [s][68] fp32 @ float 256 ----
    {
        float bc0 = __ldg(&bconv[16 * wd + r0w]);
        float bc1 = __ldg(&bconv[16 * wd + r0w + 8]);
#pragma unroll
        for (int nf = 0; nf < 4; nf++) {
            int s = 32 * ws + nf * 8 + cq * 2;
            smf[256 + s * 68 + 16 * wd + r0w]           = accl[nf][0] + bc0;
            smf[256 + (s + 1) * 68 + 16 * wd + r0w]     = accl[nf][1] + bc0;
            smf[256 + s * 68 + 16 * wd + r0w + 8]       = accl[nf][2] + bc1;
            smf[256 + (s + 1) * 68 + 16 * wd + r0w + 8] = accl[nf][3] + bc1;
        }
    }
    __syncthreads();

    // ---- softmax over K=64 per s ----
    {
        const int sidx = tid & 63, kg = tid >> 6;
        float lv[16];
        float mx = -1e30f;
#pragma unroll
        for (int i = 0; i < 16; i++) {
            lv[i] = smf[256 + sidx * 68 + kg * 16 + i];
            mx = fmaxf(mx, lv[i]);
        }
        smf[17984 + sidx * 5 + kg] = mx;
        __syncthreads();
        float M = fmaxf(fmaxf(smf[17984 + sidx * 5], smf[17984 + sidx * 5 + 1]),
                        fmaxf(smf[17984 + sidx * 5 + 2], smf[17984 + sidx * 5 + 3]));
        float es = 0.f;
#pragma unroll
        for (int i = 0; i < 16; i++) { lv[i] = __expf(lv[i] - M); es += lv[i]; }
        smf[18304 + sidx * 5 + kg] = es;
        __syncthreads();
        float tot = smf[18304 + sidx * 5] + smf[18304 + sidx * 5 + 1]
                  + smf[18304 + sidx * 5 + 2] + smf[18304 + sidx * 5 + 3];
        float r = ((s0 + sidx) < 784) ? 1.f / tot : 0.f;
#pragma unroll
        for (int i = 0; i < 16; i++)
            *(__half*)(smc + 18432 + (kg * 16 + i) * 144 + sidx * 2) =
                __float2half_rn(lv[i] * r);
    }
    __syncthreads();

    // ---- sasum from rounded sa ----
    if (tid < 64) {
        const __half2* rp = (const __half2*)(smc + 18432 + tid * 144);
        float s = 0.f;
#pragma unroll
        for (int i = 0; i < 32; i++) {
            float2 f = __half22float2(rp[i]);
            s += f.x + f.y;
        }
        atomicAdd(&g_sasum[n * 64 + tid], s);
    }

    // ---- vlad mma: M=64(k) N=128(d) K=64(s) ----
    {
        const uint32_t aV = sb + 18432 + (uint32_t)(16 * wd + ((mat & 1) << 3) + rr) * 144
                            + ((uint32_t)(mat >> 1) << 4);
        const uint32_t bV = sb + 54272 + (uint32_t)(((mat & 1) << 3) + rr) * 272
                            + (uint32_t)(64 * ws + ((mat >> 1) << 3)) * 2;
        float accv[8][4];
#pragma unroll
        for (int nf = 0; nf < 8; nf++)
#pragma unroll
            for (int u = 0; u < 4; u++) accv[nf][u] = 0.f;
#pragma unroll
        for (int ks = 0; ks < 4; ks++) {
            unsigned a[4];
            ldsm(a, aV + ks * 32);
            unsigned bb[4][4];
#pragma unroll
            for (int nt = 0; nt < 4; nt++)
                ldsmt(bb[nt], bV + ks * 4352 + nt * 32);
#pragma unroll
            for (int nf = 0; nf < 8; nf++)
                mma_f16(accv[nf], a, &bb[nf >> 1][(nf & 1) * 2]);
        }
        float* vr = g_vladraw + (size_t)n * 8192;
        const int k0 = 16 * wd + r0w, k1 = k0 + 8;
#pragma unroll
        for (int nf = 0; nf < 8; nf++) {
            int d = 64 * ws + nf * 8 + cq * 2;
            atomicAdd(&vr[k0 * 128 + d],     accv[nf][0]);
            atomicAdd(&vr[k0 * 128 + d + 1], accv[nf][1]);
            atomicAdd(&vr[k1 * 128 + d],     accv[nf][2]);
            atomicAdd(&vr[k1 * 128 + d + 1], accv[nf][3]);
        }
    }
}

// ---------------------------------------------------------------------------
// kBfin: vlad = vladraw - centroids*sasum, intra-norm over K
// ---------------------------------------------------------------------------
__global__ void __launch_bounds__(256) kBfin(const float* __restrict__ centroids) {
    __shared__ float ssm[64];
    __shared__ float red[8][33];
    const int dt = blockIdx.x, n = blockIdx.y, tid = threadIdx.x;
    const int dl = tid & 31, kg = tid >> 5;
    const int d = dt * 32 + dl;
    if (tid < 64) ssm[tid] = g_sasum[n * 64 + tid];
    __syncthreads();
    const float* vr = g_vladraw + (size_t)n * 8192;
    float v[8], sq = 0.f;
#pragma unroll
    for (int j = 0; j < 8; j++) {
        int k = kg * 8 + j;
        float val = vr[k * 128 + d] - centroids[k * 128 + d] * ssm[k];
        v[j] = val;
        sq += val * val;
    }
    red[kg][dl] = sq;
    __syncthreads();
    float tot = 0.f;
#pragma unroll
    for (int t = 0; t < 8; t++) tot += red[t][dl];
    float inv = 1.f / fmaxf(sqrtf(tot), 1e-12f);
    float* vo = g_vlad + (size_t)n * 8192;
#pragma unroll
    for (int j = 0; j < 8; j++)
        vo[(kg * 8 + j) * 128 + d] = v[j] * inv;
}

// ---------------------------------------------------------------------------
// kC: proj = vlad @ Wproj^T via fp16 HMMA.
// grid (16 o-tiles of 64, 16 j-splits of 512), 128 thr (4 warps)
// smem: Wt[b] @ b*14336 [64 o][72h, 144B rows]; Vt[b] @ b*14336+9216 [64 j][40h, 80B rows]
// ---------------------------------------------------------------------------
__global__ void __launch_bounds__(128) kC(const float* __restrict__ Wproj) {
    __shared__ __align__(16) unsigned char sm[28672];
    const int tid = threadIdx.x, lane = tid & 31, w = tid >> 5;
    const int ob = blockIdx.x * 64;
    const int jb = blockIdx.y * 512;
    const int mat = lane >> 3, rr = lane & 7;
    const uint32_t sb = smem_u32(sm);

    float acc[4][4];
#pragma unroll
    for (int nf = 0; nf < 4; nf++)
#pragma unroll
        for (int u = 0; u < 4; u++) acc[nf][u] = 0.f;

    const int wrow = tid >> 1, wcol = (tid & 1) * 32;  // W: 64 rows, 32 j each
    const int vn = tid >> 2, vj = (tid & 3) * 16;      // V: 32 n, 16 j each

    float4 wreg[8];
    float4 vreg[4];

#define LOADC(c) do { \
    const float* wp = Wproj + (size_t)(ob + wrow) * 8192 + jb + (c) * 64 + wcol; \
    _Pragma("unroll") \
    for (int u = 0; u < 8; u++) wreg[u] = ((const float4*)wp)[u]; \
    const float* vp = g_vlad + (size_t)vn * 8192 + jb + (c) * 64 + vj; \
    _Pragma("unroll") \
    for (int u = 0; u < 4; u++) vreg[u] = ((const float4*)vp)[u]; \
    } while (0)

#define STOREC(b) do { \
    unsigned char* wdst = sm + (b) * 14336 + wrow * 144 + wcol * 2; \
    _Pragma("unroll") \
    for (int u = 0; u < 8; u++) { \
        __half2 h0 = __floats2half2_rn(wreg[u].x, wreg[u].y); \
        __half2 h1 = __floats2half2_rn(wreg[u].z, wreg[u].w); \
        *(uint32_t*)(wdst + u * 8)     = *(uint32_t*)&h0; \
        *(uint32_t*)(wdst + u * 8 + 4) = *(uint32_t*)&h1; \
    } \
    unsigned char* vdst = sm + (b) * 14336 + 9216; \
    _Pragma("unroll") \
    for (int u = 0; u < 4; u++) { \
        int jl = vj + u * 4; \
        *(__half*)(vdst + (jl + 0) * 80 + vn * 2) = __float2half_rn(vreg[u].x); \
        *(__half*)(vdst + (jl + 1) * 80 + vn * 2) = __float2half_rn(vreg[u].y); \
        *(__half*)(vdst + (jl + 2) * 80 + vn * 2) = __float2half_rn(vreg[u].z); \
        *(__half*)(vdst + (jl + 3) * 80 + vn * 2) = __float2half_rn(vreg[u].w); \
    } } while (0)

    const uint32_t aB0 = sb + (uint32_t)(w * 16 + ((mat & 1) << 3) + rr) * 144
                         + ((uint32_t)(mat >> 1) << 4);
    const uint32_t bB0 = sb + 9216 + (uint32_t)(((mat & 1) << 3) + rr) * 80
                         + ((uint32_t)(mat >> 1) << 4);

    LOADC(0);
    for (int c = 0; c < 8; c++) {
        const int b = c & 1;
        STOREC(b);
        if (c + 1 < 8) LOADC(c + 1);
        __syncthreads();
        const uint32_t aB = aB0 + b * 14336;
        const uint32_t bB = bB0 + b * 14336;
#pragma unroll
        for (int ks = 0; ks < 4; ks++) {
            unsigned a[4];
            ldsm(a, aB + ks * 32);
            unsigned bb[2][4];
            ldsmt(bb[0], bB + ks * 1280);
            ldsmt(bb[1], bB + ks * 1280 + 32);
#pragma unroll
            for (int nf = 0; nf < 4; nf++)
                mma_f16(acc[nf], a, &bb[nf >> 1][(nf & 1) * 2]);
        }
        __syncthreads();
    }
#undef LOADC
#undef STOREC

    // C fragment: row = o (lane>>2 [+8]), col = n (nf*8 + (lane&3)*2 [+1])
    {
        const int o0 = ob + w * 16 + (lane >> 2);
        const int o1 = o0 + 8;
#pragma unroll
        for (int nf = 0; nf < 4; nf++) {
            int n0 = nf * 8 + (lane & 3) * 2;
            atomicAdd(&g_proj[(n0 + 0) * 1024 + o0], acc[nf][0]);
            atomicAdd(&g_proj[(n0 + 1) * 1024 + o0], acc[nf][1]);
            atomicAdd(&g_proj[(n0 + 0) * 1024 + o1], acc[nf][2]);
            atomicAdd(&g_proj[(n0 + 1) * 1024 + o1], acc[nf][3]);
        }
    }
}

// ---------------------------------------------------------------------------
__global__ void __launch_bounds__(256) kD(const float* __restrict__ bproj,
                                          float* __restrict__ out) {
    __shared__ float wr[8];
    __shared__ float inv_s;
    const int n = blockIdx.x, tid = threadIdx.x;
    float v[4]; float ps = 0.f;
#pragma unroll
    for (int r = 0; r < 4; r++) {
        int o = r * 256 + tid;
        v[r] = g_proj[n * 1024 + o] + bproj[o];
        ps += v[r] * v[r];
    }
#pragma unroll
    for (int off = 16; off; off >>= 1)
        ps += __shfl_xor_sync(0xffffffffu, ps, off);
    if ((tid & 31) == 0) wr[tid >> 5] = ps;
    __syncthreads();
    if (tid == 0) {
        float s = 0.f;
#pragma unroll
        for (int t = 0; t < 8; t++) s += wr[t];
        inv_s = 1.f / fmaxf(sqrtf(s), 1e-12f);
    }
    __syncthreads();
#pragma unroll
    for (int r = 0; r < 4; r++)
        out[n * 1024 + r * 256 + tid] = v[r] * inv_s;
}

// ---------------------------------------------------------------------------
extern "C" void kernel_launch(void* const* d_in, const int* in_sizes, int n_in,
                              void* d_out, int out_size) {
    const float* x         = (const float*)d_in[0];
    const float* Wpool     = (const float*)d_in[1];
    const float* bpool     = (const float*)d_in[2];
    const float* Wconv     = (const float*)d_in[3];
    const float* bconv     = (const float*)d_in[4];
    const float* centroids = (const float*)d_in[5];
    const float* Wproj     = (const float*)d_in[6];
    const float* bproj     = (const float*)d_in[7];
    float* out = (float*)d_out;

    cudaFuncSetAttribute(kA, cudaFuncAttributeMaxDynamicSharedMemorySize, 93184);

    kW<<<512, 256>>>(Wpool);
    kZ<<<1024, 256>>>(Wconv);
    dim3 gA(13, 32);
    kA<<<gA, 256, 93184>>>(x, bpool, bconv);
    dim3 gB(4, 32);
    kBfin<<<gB, 256>>>(centroids);
    dim3 gC(16, 16);
    kC<<<gC, 128>>>(Wproj);
    kD<<<32, 256>>>(bproj, out);
}